// round 1
// baseline (speedup 1.0000x reference)
#include <cuda_runtime.h>
#include <math.h>

#define BB 2
#define CC 16
#define DD 64
#define HHV 64
#define WWV 64
#define NV (DD*HHV*WWV)          // 262144
#define HDIM 128
#define WDIM 128
#define PPN 3

// Scratch (static device arrays; allocation-free per harness rules).
// g_xi is reused as the 'h' buffer after the offset/mask convs consume it.
__device__ float g_xi[BB*CC*NV];      // 33.5 MB : xi, later h
__device__ float g_om[BB*9*NV];       // 18.9 MB : 6 offset + 3 mask channels
__device__ float g_xsum[BB*CC*NV];    // 33.5 MB : deformable-attention sum

// Closed-form replication of _xray_coords for theta=pi, phi=0, gamma=pi/2,
// sdr=200, del=2, spacing=1, D=H=W=64, Hd=Wd=128:
//   source=(-168,32,32), center=(232,32,32), wgt=400/(d+168)
//   Xc_y=((wgt*(h-32)+32)+95)/2, Xc_x=((wgt*(w-32)+32)+95)/2
// Computed in double then cast to float to match numpy float64 -> float32.
__device__ __forceinline__ void xray_coords(int d, int h, int w, float& py, float& px) {
    double wgt = 400.0 / (double)(d + 168);
    py = (float)(((wgt * (double)(h - 32) + 32.0) + 95.0) * 0.5);
    px = (float)(((wgt * (double)(w - 32) + 32.0) + 95.0) * 0.5);
}

// ---------------------------------------------------------------------------
// Kernel 1: xi = bilinear sample of Xray at Xrc (coords are interior: no clamp
// ever fires; corner-weight formulas reduce to standard bilinear).
// ---------------------------------------------------------------------------
__global__ void xi_kernel(const float* __restrict__ Xray, float* __restrict__ xi) {
    int idx = blockIdx.x * blockDim.x + threadIdx.x;
    if (idx >= BB * NV) return;
    int w = idx & 63, h = (idx >> 6) & 63, d = (idx >> 12) & 63, b = idx >> 18;
    int vox = idx & (NV - 1);

    float py, px;
    xray_coords(d, h, w, py, px);
    float fy = floorf(py), fx = floorf(px);
    int y0 = (int)fy, x0 = (int)fx;
    float ay = py - fy, ax = px - fx;
    float wlt = (1.f - ay) * (1.f - ax);
    float wrb = ay * ax;
    float wrt = (1.f - ay) * ax;
    float wlb = ay * (1.f - ax);

    const float* Xb = Xray + (size_t)b * CC * HDIM * WDIM;
    int i00 = y0 * WDIM + x0;
#pragma unroll
    for (int c = 0; c < CC; c++) {
        const float* p = Xb + (size_t)c * HDIM * WDIM;
        float v = wlt * p[i00] + wrt * p[i00 + 1]
                + wlb * p[i00 + WDIM] + wrb * p[i00 + WDIM + 1];
        xi[((size_t)(b * CC + c)) * NV + vox] = v;
    }
}

// ---------------------------------------------------------------------------
// Generic 3x3x3 conv, padding 1. Input channels: cin<16 from inA (CT),
// cin>=16 from inB (xi or Xsum). 8x8x8 output tile per 512-thread block,
// 10x10x10 halo tile in SMEM, per-cin weight slab in SMEM, Cout accumulators
// in registers. Optional BN + leaky(0.2) epilogue.
// ---------------------------------------------------------------------------
template<int CIN, int COUT, bool DOBN>
__global__ __launch_bounds__(512)
void conv3_kernel(const float* __restrict__ inA, const float* __restrict__ inB,
                  const float* __restrict__ Wt, const float* __restrict__ bias,
                  float* __restrict__ out, int ostride, int cobase,
                  const float* __restrict__ gamma, const float* __restrict__ beta,
                  const float* __restrict__ mean, const float* __restrict__ var) {
    __shared__ float s_t[1000];        // 10*10*10 halo tile
    __shared__ float s_w[COUT * 27];   // weights for current cin

    int bi = blockIdx.x;
    int tx = (bi & 7) * 8, ty = ((bi >> 3) & 7) * 8, tz = ((bi >> 6) & 7) * 8;
    int b = bi >> 9;
    int tid = threadIdx.x;
    int lx = tid & 7, ly = (tid >> 3) & 7, lz = tid >> 6;

    float acc[COUT];
#pragma unroll
    for (int co = 0; co < COUT; co++) acc[co] = 0.f;

    for (int cin = 0; cin < CIN; cin++) {
        __syncthreads();
        const float* src = (cin < 16)
            ? inA + ((size_t)(b * 16 + cin)) * NV
            : inB + ((size_t)(b * 16 + (cin - 16))) * NV;
        // halo tile load, zero-padded at volume borders
        for (int i = tid; i < 1000; i += 512) {
            int z = i / 100, r = i - z * 100, y = r / 10, x = r - y * 10;
            int gz = tz + z - 1, gy = ty + y - 1, gx = tx + x - 1;
            float v = 0.f;
            if ((unsigned)gz < 64u && (unsigned)gy < 64u && (unsigned)gx < 64u)
                v = src[(gz << 12) + (gy << 6) + gx];
            s_t[i] = v;
        }
        // weight slab for this cin: layout [co*27 + tap]
        for (int j = tid; j < COUT * 27; j += 512) {
            int co = j / 27, tap = j - co * 27;
            s_w[j] = Wt[(size_t)co * (CIN * 27) + cin * 27 + tap];
        }
        __syncthreads();

#pragma unroll
        for (int kd = 0; kd < 3; kd++)
#pragma unroll
            for (int kh = 0; kh < 3; kh++)
#pragma unroll
                for (int kw = 0; kw < 3; kw++) {
                    float v = s_t[(lz + kd) * 100 + (ly + kh) * 10 + (lx + kw)];
                    int wb = kd * 9 + kh * 3 + kw;
#pragma unroll
                    for (int co = 0; co < COUT; co++)
                        acc[co] += v * s_w[co * 27 + wb];
                }
    }

    int gz = tz + lz, gy = ty + ly, gx = tx + lx;
    size_t vox = (size_t)((gz << 12) + (gy << 6) + gx);
#pragma unroll
    for (int co = 0; co < COUT; co++) {
        float v = acc[co] + bias[co];
        if (DOBN) {
            v = (v - mean[co]) * rsqrtf(var[co] + 1e-5f) * gamma[co] + beta[co];
            v = (v >= 0.f) ? v : 0.2f * v;
        }
        out[((size_t)(b * ostride + cobase + co)) * NV + vox] = v;
    }
}

// ---------------------------------------------------------------------------
// Kernel 3: softmax(mask) + deformable bilinear gather on the zero-padded
// 130x130 Xray, writes Xsum and the p_coor output. Implements the reference's
// clipped-corner weight formulas exactly (clip to [0,129] on the padded grid);
// pad is implicit: indices touching row/col 0 or 129 read 0.
// ---------------------------------------------------------------------------
__global__ void deform_kernel(const float* __restrict__ Xray, const float* __restrict__ om,
                              float* __restrict__ xsum, float* __restrict__ pcoor) {
    int idx = blockIdx.x * blockDim.x + threadIdx.x;
    if (idx >= BB * NV) return;
    int w = idx & 63, h = (idx >> 6) & 63, d = (idx >> 12) & 63, b = idx >> 18;
    int vox = idx & (NV - 1);

    const float* omb = om + (size_t)b * 9 * NV;
    float off[6];
#pragma unroll
    for (int j = 0; j < 6; j++) off[j] = omb[(size_t)j * NV + vox];
    float m0 = omb[(size_t)6 * NV + vox];
    float m1 = omb[(size_t)7 * NV + vox];
    float m2 = omb[(size_t)8 * NV + vox];
    float mx = fmaxf(m0, fmaxf(m1, m2));
    float e0 = expf(m0 - mx), e1 = expf(m1 - mx), e2 = expf(m2 - mx);
    float inv = 1.f / (e0 + e1 + e2);
    float mm[3] = { e0 * inv, e1 * inv, e2 * inv };

    float py0, px0;
    xray_coords(d, h, w, py0, px0);

    int   idx4[PPN][4];
    float wgt4[PPN][4];
#pragma unroll
    for (int p = 0; p < PPN; p++) {
        float py = fminf(fmaxf(off[p] + py0 + 1.f, 0.f), (float)(HDIM + 1));
        float px = fminf(fmaxf(off[PPN + p] + px0 + 1.f, 0.f), (float)(WDIM + 1));
        pcoor[(size_t)idx * 6 + p]        = py;
        pcoor[(size_t)idx * 6 + PPN + p]  = px;

        int fy = (int)floorf(py), fx = (int)floorf(px);
        int y0 = min(fy, HDIM + 1),     y1 = min(fy + 1, HDIM + 1);
        int x0 = min(fx, WDIM + 1),     x1 = min(fx + 1, WDIM + 1);
        float wy0 = 1.f + (float)y0 - py;
        float wy1 = 1.f - ((float)y1 - py);
        float wx0 = 1.f + (float)x0 - px;
        float wx1 = 1.f - ((float)x1 - px);

        // padded (130x130) index -> raw Xray index, -1 if in the zero pad
        int e00 = (y0 >= 1 && y0 <= HDIM && x0 >= 1 && x0 <= WDIM) ? ((y0 - 1) * WDIM + (x0 - 1)) : -1;
        int e11 = (y1 >= 1 && y1 <= HDIM && x1 >= 1 && x1 <= WDIM) ? ((y1 - 1) * WDIM + (x1 - 1)) : -1;
        int e01 = (y0 >= 1 && y0 <= HDIM && x1 >= 1 && x1 <= WDIM) ? ((y0 - 1) * WDIM + (x1 - 1)) : -1;
        int e10 = (y1 >= 1 && y1 <= HDIM && x0 >= 1 && x0 <= WDIM) ? ((y1 - 1) * WDIM + (x0 - 1)) : -1;
        idx4[p][0] = e00; idx4[p][1] = e11; idx4[p][2] = e01; idx4[p][3] = e10;
        wgt4[p][0] = mm[p] * wy0 * wx0;
        wgt4[p][1] = mm[p] * wy1 * wx1;
        wgt4[p][2] = mm[p] * wy0 * wx1;
        wgt4[p][3] = mm[p] * wy1 * wx0;
    }

    const float* Xb = Xray + (size_t)b * CC * HDIM * WDIM;
#pragma unroll
    for (int c = 0; c < CC; c++) {
        const float* pl = Xb + (size_t)c * HDIM * WDIM;
        float s = 0.f;
#pragma unroll
        for (int p = 0; p < PPN; p++)
#pragma unroll
            for (int q = 0; q < 4; q++) {
                int i4 = idx4[p][q];
                float v = (i4 >= 0) ? pl[i4] : 0.f;
                s += wgt4[p][q] * v;
            }
        xsum[((size_t)(b * CC + c)) * NV + vox] = s;
    }
}

// ---------------------------------------------------------------------------
// Launch. Output layout: [ conv2 out (B,C,D,H,W) | p_coor (B,D,H,W,6) ].
// ---------------------------------------------------------------------------
extern "C" void kernel_launch(void* const* d_in, const int* in_sizes, int n_in,
                              void* d_out, int out_size) {
    const float* CT    = (const float*)d_in[0];
    const float* Xray  = (const float*)d_in[1];
    const float* pW    = (const float*)d_in[2];
    const float* pb    = (const float*)d_in[3];
    const float* mW    = (const float*)d_in[4];
    const float* mb    = (const float*)d_in[5];
    const float* w1    = (const float*)d_in[6];
    const float* b1    = (const float*)d_in[7];
    const float* w2    = (const float*)d_in[8];
    const float* b2    = (const float*)d_in[9];
    const float* gamma = (const float*)d_in[10];
    const float* beta  = (const float*)d_in[11];
    const float* mean  = (const float*)d_in[12];
    const float* var   = (const float*)d_in[13];

    float* xi_p; cudaGetSymbolAddress((void**)&xi_p, g_xi);
    float* om_p; cudaGetSymbolAddress((void**)&om_p, g_om);
    float* xs_p; cudaGetSymbolAddress((void**)&xs_p, g_xsum);

    float* out   = (float*)d_out;
    float* pcoor = out + (size_t)BB * CC * NV;   // 8388608

    const int nthr = 256;
    const int nblk = (BB * NV + nthr - 1) / nthr;   // 2048
    const int cblk = BB * 8 * 8 * 8;                // 1024 conv tiles

    // 1) xi = bilerp_single(Xrc, Xray)
    xi_kernel<<<nblk, nthr>>>(Xray, xi_p);
    // 2) offset conv (6 out) and mask conv (3 out) over [CT | xi]
    conv3_kernel<32, 6, false><<<cblk, 512>>>(CT, xi_p, pW, pb, om_p, 9, 0,
                                              nullptr, nullptr, nullptr, nullptr);
    conv3_kernel<32, 3, false><<<cblk, 512>>>(CT, xi_p, mW, mb, om_p, 9, 6,
                                              nullptr, nullptr, nullptr, nullptr);
    // 3) softmax + deformable gather -> Xsum, p_coor
    deform_kernel<<<nblk, nthr>>>(Xray, om_p, xs_p, pcoor);
    // 4) conv1 over [CT | Xsum] + BN + leaky -> h (reuses g_xi)
    conv3_kernel<32, 16, true><<<cblk, 512>>>(CT, xs_p, w1, b1, xi_p, 16, 0,
                                              gamma, beta, mean, var);
    // 5) conv2 (16->16) -> final output
    conv3_kernel<16, 16, false><<<cblk, 512>>>(xi_p, nullptr, w2, b2, out, 16, 0,
                                               nullptr, nullptr, nullptr, nullptr);
}

// round 5
// speedup vs baseline: 2.0265x; 2.0265x over previous
#include <cuda_runtime.h>
#include <math.h>

#define BB 2
#define CC 16
#define NV (64*64*64)            // 262144
#define HDIM 128
#define WDIM 128
#define PPN 3

// Scratch (static device arrays; allocation-free per harness rules).
// g_xi is reused as the 'h' buffer after the offset/mask conv consumes it.
__device__ float g_xi[BB*CC*NV];      // 33.5 MB : xi, later h
__device__ float g_om[BB*9*NV];       // 18.9 MB : 6 offset + 3 mask channels
__device__ float g_xsum[BB*CC*NV];    // 33.5 MB : deformable-attention sum

// Packed dual-fp32 FMA (sm_100+): d = a*b + c elementwise on two fp32 lanes.
__device__ __forceinline__ unsigned long long fma2(unsigned long long a,
                                                   unsigned long long b,
                                                   unsigned long long c) {
    unsigned long long d;
    asm("fma.rn.f32x2 %0, %1, %2, %3;" : "=l"(d) : "l"(a), "l"(b), "l"(c));
    return d;
}

// Closed-form replication of _xray_coords for theta=pi, phi=0, gamma=pi/2,
// sdr=200, del=2, spacing=1, D=H=W=64, Hd=Wd=128. Double then cast to float
// to match numpy float64 -> float32.
__device__ __forceinline__ void xray_coords(int d, int h, int w, float& py, float& px) {
    double wgt = 400.0 / (double)(d + 168);
    py = (float)(((wgt * (double)(h - 32) + 32.0) + 95.0) * 0.5);
    px = (float)(((wgt * (double)(w - 32) + 32.0) + 95.0) * 0.5);
}

// ---------------------------------------------------------------------------
// Kernel 1: xi = bilinear sample of Xray at Xrc (coords interior, no clamps).
// ---------------------------------------------------------------------------
__global__ void xi_kernel(const float* __restrict__ Xray, float* __restrict__ xi) {
    int idx = blockIdx.x * blockDim.x + threadIdx.x;
    if (idx >= BB * NV) return;
    int w = idx & 63, h = (idx >> 6) & 63, d = (idx >> 12) & 63, b = idx >> 18;
    int vox = idx & (NV - 1);

    float py, px;
    xray_coords(d, h, w, py, px);
    float fy = floorf(py), fx = floorf(px);
    int y0 = (int)fy, x0 = (int)fx;
    float ay = py - fy, ax = px - fx;
    float wlt = (1.f - ay) * (1.f - ax);
    float wrb = ay * ax;
    float wrt = (1.f - ay) * ax;
    float wlb = ay * (1.f - ax);

    const float* Xb = Xray + (size_t)b * CC * HDIM * WDIM;
    int i00 = y0 * WDIM + x0;
#pragma unroll
    for (int c = 0; c < CC; c++) {
        const float* p = Xb + (size_t)c * HDIM * WDIM;
        float v = wlt * p[i00] + wrt * p[i00 + 1]
                + wlb * p[i00 + WDIM] + wrb * p[i00 + WDIM + 1];
        xi[((size_t)(b * CC + c)) * NV + vox] = v;
    }
}

// ---------------------------------------------------------------------------
// 3x3x3 conv, pad 1, f32x2-packed over output-channel pairs with 4-voxel
// x-blocking per thread. 128 threads/block; output tile 16(x) x 8(y) x 4(z).
// Halo tile 18x10x6 stored DUPLICATED (v,v) as float2 with row stride 19
// (bank-conflict-free LDS.64). Weights in SMEM as [tap][co], co contiguous,
// so a co-pair is one LDS.64.
// MODE 0: plain (+bias).  MODE 1: +BN+leaky.  MODE 2: fused offset(6)+mask(3)
// convs, COUTP=10 with a zero-padded 10th channel (not stored).
// ---------------------------------------------------------------------------
template<int CIN, int COUTP, int MODE>
__global__ __launch_bounds__(128)
void conv3_f2(const float* __restrict__ inA, const float* __restrict__ inB,
              const float* __restrict__ WtA, const float* __restrict__ bAv,
              const float* __restrict__ WtB, const float* __restrict__ bBv,
              float* __restrict__ out,
              const float* __restrict__ gamma, const float* __restrict__ beta,
              const float* __restrict__ mean, const float* __restrict__ var) {
    constexpr int NCP = COUTP / 2;
    __shared__ __align__(16) float2 s_t[6 * 10 * 19];   // 9120 B, (v,v) pairs
    __shared__ __align__(16) float  s_w[27 * COUTP];

    int bi = blockIdx.x;
    int xt = bi & 3, yt = (bi >> 2) & 7, zt = (bi >> 5) & 15, b = bi >> 9;
    int tx = xt * 16, ty = yt * 8, tz = zt * 4;
    int tid = threadIdx.x;
    int lx4 = tid & 3, ly = (tid >> 2) & 7, lz = tid >> 5;

    unsigned long long acc[NCP][4];
#pragma unroll
    for (int cp = 0; cp < NCP; cp++)
#pragma unroll
        for (int x = 0; x < 4; x++) acc[cp][x] = 0ull;

    for (int cin = 0; cin < CIN; cin++) {
        __syncthreads();
        const float* src = (CIN == 32 && cin >= 16)
            ? inB + ((size_t)(b * 16 + (cin - 16))) * NV
            : inA + ((size_t)(b * 16 + cin)) * NV;

        // halo tile, zero-padded at borders, duplicated (v,v)
        for (int i = tid; i < 1080; i += 128) {
            int z = i / 180, r = i - z * 180, y = r / 18, x = r - y * 18;
            int gz = tz + z - 1, gy = ty + y - 1, gx = tx + x - 1;
            float v = 0.f;
            if ((unsigned)gz < 64u && (unsigned)gy < 64u && (unsigned)gx < 64u)
                v = src[(gz << 12) + (gy << 6) + gx];
            s_t[(z * 10 + y) * 19 + x] = make_float2(v, v);
        }
        // weight slab [tap][co] for this cin
        for (int j = tid; j < 27 * COUTP; j += 128) {
            int tap = j / COUTP, co = j - tap * COUTP;
            float wv;
            if (MODE == 2) {
                wv = (co < 6) ? WtA[(size_t)co * (CIN * 27) + cin * 27 + tap]
                   : (co < 9) ? WtB[(size_t)(co - 6) * (CIN * 27) + cin * 27 + tap]
                   : 0.f;
            } else {
                wv = WtA[(size_t)co * (CIN * 27) + cin * 27 + tap];
            }
            s_w[tap * COUTP + co] = wv;
        }
        __syncthreads();

        const unsigned long long* wt =
            reinterpret_cast<const unsigned long long*>(s_w);
#pragma unroll
        for (int kd = 0; kd < 3; kd++)
#pragma unroll
            for (int kh = 0; kh < 3; kh++) {
                const unsigned long long* row =
                    reinterpret_cast<const unsigned long long*>(s_t)
                    + ((lz + kd) * 10 + (ly + kh)) * 19 + lx4 * 4;
                unsigned long long vp[6];
#pragma unroll
                for (int j = 0; j < 6; j++) vp[j] = row[j];
#pragma unroll
                for (int kw = 0; kw < 3; kw++) {
                    int tb = (kd * 9 + kh * 3 + kw) * NCP;
#pragma unroll
                    for (int cp = 0; cp < NCP; cp++) {
                        unsigned long long w = wt[tb + cp];
                        acc[cp][0] = fma2(vp[kw + 0], w, acc[cp][0]);
                        acc[cp][1] = fma2(vp[kw + 1], w, acc[cp][1]);
                        acc[cp][2] = fma2(vp[kw + 2], w, acc[cp][2]);
                        acc[cp][3] = fma2(vp[kw + 3], w, acc[cp][3]);
                    }
                }
            }
    }

    int gx = tx + lx4 * 4, gy = ty + ly, gz = tz + lz;
    size_t vox = (size_t)((gz << 12) + (gy << 6) + gx);
    constexpr int OST = (MODE == 2) ? 9 : 16;
#pragma unroll
    for (int cp = 0; cp < NCP; cp++) {
        float2 a0 = *reinterpret_cast<float2*>(&acc[cp][0]);
        float2 a1 = *reinterpret_cast<float2*>(&acc[cp][1]);
        float2 a2 = *reinterpret_cast<float2*>(&acc[cp][2]);
        float2 a3 = *reinterpret_cast<float2*>(&acc[cp][3]);
#pragma unroll
        for (int half = 0; half < 2; half++) {
            int co = 2 * cp + half;
            if (MODE == 2 && co >= 9) continue;
            float4 o;
            o.x = half ? a0.y : a0.x;
            o.y = half ? a1.y : a1.x;
            o.z = half ? a2.y : a2.x;
            o.w = half ? a3.y : a3.x;
            float bia = (MODE == 2) ? ((co < 6) ? bAv[co] : bBv[co - 6]) : bAv[co];
            o.x += bia; o.y += bia; o.z += bia; o.w += bia;
            if (MODE == 1) {
                float sc = rsqrtf(var[co] + 1e-5f) * gamma[co];
                float mu = mean[co], be = beta[co];
                o.x = (o.x - mu) * sc + be; o.x = (o.x >= 0.f) ? o.x : 0.2f * o.x;
                o.y = (o.y - mu) * sc + be; o.y = (o.y >= 0.f) ? o.y : 0.2f * o.y;
                o.z = (o.z - mu) * sc + be; o.z = (o.z >= 0.f) ? o.z : 0.2f * o.z;
                o.w = (o.w - mu) * sc + be; o.w = (o.w >= 0.f) ? o.w : 0.2f * o.w;
            }
            *reinterpret_cast<float4*>(&out[((size_t)(b * OST + co)) * NV + vox]) = o;
        }
    }
}

// ---------------------------------------------------------------------------
// Kernel 3: softmax(mask) + deformable bilinear gather on the zero-padded
// 130x130 Xray; writes Xsum and the p_coor output (exact reference formulas).
// ---------------------------------------------------------------------------
__global__ void deform_kernel(const float* __restrict__ Xray, const float* __restrict__ om,
                              float* __restrict__ xsum, float* __restrict__ pcoor) {
    int idx = blockIdx.x * blockDim.x + threadIdx.x;
    if (idx >= BB * NV) return;
    int w = idx & 63, h = (idx >> 6) & 63, d = (idx >> 12) & 63, b = idx >> 18;
    int vox = idx & (NV - 1);

    const float* omb = om + (size_t)b * 9 * NV;
    float off[6];
#pragma unroll
    for (int j = 0; j < 6; j++) off[j] = omb[(size_t)j * NV + vox];
    float m0 = omb[(size_t)6 * NV + vox];
    float m1 = omb[(size_t)7 * NV + vox];
    float m2 = omb[(size_t)8 * NV + vox];
    float mx = fmaxf(m0, fmaxf(m1, m2));
    float e0 = expf(m0 - mx), e1 = expf(m1 - mx), e2 = expf(m2 - mx);
    float inv = 1.f / (e0 + e1 + e2);
    float mm[3] = { e0 * inv, e1 * inv, e2 * inv };

    float py0, px0;
    xray_coords(d, h, w, py0, px0);

    int   idx4[PPN][4];
    float wgt4[PPN][4];
#pragma unroll
    for (int p = 0; p < PPN; p++) {
        float py = fminf(fmaxf(off[p] + py0 + 1.f, 0.f), (float)(HDIM + 1));
        float px = fminf(fmaxf(off[PPN + p] + px0 + 1.f, 0.f), (float)(WDIM + 1));
        pcoor[(size_t)idx * 6 + p]        = py;
        pcoor[(size_t)idx * 6 + PPN + p]  = px;

        int fy = (int)floorf(py), fx = (int)floorf(px);
        int y0 = min(fy, HDIM + 1),     y1 = min(fy + 1, HDIM + 1);
        int x0 = min(fx, WDIM + 1),     x1 = min(fx + 1, WDIM + 1);
        float wy0 = 1.f + (float)y0 - py;
        float wy1 = 1.f - ((float)y1 - py);
        float wx0 = 1.f + (float)x0 - px;
        float wx1 = 1.f - ((float)x1 - px);

        int e00 = (y0 >= 1 && y0 <= HDIM && x0 >= 1 && x0 <= WDIM) ? ((y0 - 1) * WDIM + (x0 - 1)) : -1;
        int e11 = (y1 >= 1 && y1 <= HDIM && x1 >= 1 && x1 <= WDIM) ? ((y1 - 1) * WDIM + (x1 - 1)) : -1;
        int e01 = (y0 >= 1 && y0 <= HDIM && x1 >= 1 && x1 <= WDIM) ? ((y0 - 1) * WDIM + (x1 - 1)) : -1;
        int e10 = (y1 >= 1 && y1 <= HDIM && x0 >= 1 && x0 <= WDIM) ? ((y1 - 1) * WDIM + (x0 - 1)) : -1;
        idx4[p][0] = e00; idx4[p][1] = e11; idx4[p][2] = e01; idx4[p][3] = e10;
        wgt4[p][0] = mm[p] * wy0 * wx0;
        wgt4[p][1] = mm[p] * wy1 * wx1;
        wgt4[p][2] = mm[p] * wy0 * wx1;
        wgt4[p][3] = mm[p] * wy1 * wx0;
    }

    const float* Xb = Xray + (size_t)b * CC * HDIM * WDIM;
#pragma unroll
    for (int c = 0; c < CC; c++) {
        const float* pl = Xb + (size_t)c * HDIM * WDIM;
        float s = 0.f;
#pragma unroll
        for (int p = 0; p < PPN; p++)
#pragma unroll
            for (int q = 0; q < 4; q++) {
                int i4 = idx4[p][q];
                float v = (i4 >= 0) ? pl[i4] : 0.f;
                s += wgt4[p][q] * v;
            }
        xsum[((size_t)(b * CC + c)) * NV + vox] = s;
    }
}

// ---------------------------------------------------------------------------
// Launch. Output layout: [ conv2 out (B,C,D,H,W) | p_coor (B,D,H,W,6) ].
// ---------------------------------------------------------------------------
extern "C" void kernel_launch(void* const* d_in, const int* in_sizes, int n_in,
                              void* d_out, int out_size) {
    const float* CT    = (const float*)d_in[0];
    const float* Xray  = (const float*)d_in[1];
    const float* pW    = (const float*)d_in[2];
    const float* pb    = (const float*)d_in[3];
    const float* mW    = (const float*)d_in[4];
    const float* mb    = (const float*)d_in[5];
    const float* w1    = (const float*)d_in[6];
    const float* b1    = (const float*)d_in[7];
    const float* w2    = (const float*)d_in[8];
    const float* b2    = (const float*)d_in[9];
    const float* gamma = (const float*)d_in[10];
    const float* beta  = (const float*)d_in[11];
    const float* mean  = (const float*)d_in[12];
    const float* var   = (const float*)d_in[13];

    float* xi_p; cudaGetSymbolAddress((void**)&xi_p, g_xi);
    float* om_p; cudaGetSymbolAddress((void**)&om_p, g_om);
    float* xs_p; cudaGetSymbolAddress((void**)&xs_p, g_xsum);

    float* out   = (float*)d_out;
    float* pcoor = out + (size_t)BB * CC * NV;   // 8388608

    const int nthr = 256;
    const int nblk = (BB * NV + nthr - 1) / nthr;   // 2048
    const int cblk = 4 * 8 * 16 * BB;               // 1024 conv tiles

    // 1) xi = bilerp_single(Xrc, Xray)
    xi_kernel<<<nblk, nthr>>>(Xray, xi_p);
    // 2) fused offset(6)+mask(3) conv over [CT | xi]  (COUTP=10, ch 9 zero)
    conv3_f2<32, 10, 2><<<cblk, 128>>>(CT, xi_p, pW, pb, mW, mb, om_p,
                                       nullptr, nullptr, nullptr, nullptr);
    // 3) softmax + deformable gather -> Xsum, p_coor
    deform_kernel<<<nblk, nthr>>>(Xray, om_p, xs_p, pcoor);
    // 4) conv1 over [CT | Xsum] + BN + leaky -> h (reuses g_xi)
    conv3_f2<32, 16, 1><<<cblk, 128>>>(CT, xs_p, w1, b1, nullptr, nullptr, xi_p,
                                       gamma, beta, mean, var);
    // 5) conv2 (16->16) -> final output
    conv3_f2<16, 16, 0><<<cblk, 128>>>(xi_p, nullptr, w2, b2, nullptr, nullptr, out,
                                       nullptr, nullptr, nullptr, nullptr);
}

// round 8
// speedup vs baseline: 2.5681x; 1.2673x over previous
#include <cuda_runtime.h>
#include <math.h>

#define BB 2
#define CC 16
#define NV (64*64*64)            // 262144
#define HDIM 128
#define WDIM 128
#define PPN 3

// Scratch (static device arrays; allocation-free per harness rules).
__device__ float g_xi[BB*CC*NV];      // 33.5 MB : xi, later h
__device__ float g_om[BB*9*NV];       // 18.9 MB : 6 offset + 3 mask channels
__device__ float g_xsum[BB*CC*NV];    // 33.5 MB : deformable-attention sum

// Packed dual-fp32 FMA (sm_100+): d = a*b + c elementwise on two fp32 lanes.
__device__ __forceinline__ unsigned long long fma2(unsigned long long a,
                                                   unsigned long long b,
                                                   unsigned long long c) {
    unsigned long long d;
    asm("fma.rn.f32x2 %0, %1, %2, %3;" : "=l"(d) : "l"(a), "l"(b), "l"(c));
    return d;
}

// Closed-form _xray_coords (theta=pi, phi=0, gamma=pi/2, sdr=200, del=2,
// spacing=1, D=H=W=64, Hd=Wd=128); double then cast matches numpy f64->f32.
__device__ __forceinline__ void xray_coords(int d, int h, int w, float& py, float& px) {
    double wgt = 400.0 / (double)(d + 168);
    py = (float)(((wgt * (double)(h - 32) + 32.0) + 95.0) * 0.5);
    px = (float)(((wgt * (double)(w - 32) + 32.0) + 95.0) * 0.5);
}

// ---------------------------------------------------------------------------
// Kernel 1: xi = bilinear sample of Xray at Xrc (coords interior, no clamps).
// ---------------------------------------------------------------------------
__global__ void xi_kernel(const float* __restrict__ Xray, float* __restrict__ xi) {
    int idx = blockIdx.x * blockDim.x + threadIdx.x;
    if (idx >= BB * NV) return;
    int w = idx & 63, h = (idx >> 6) & 63, d = (idx >> 12) & 63, b = idx >> 18;
    int vox = idx & (NV - 1);

    float py, px;
    xray_coords(d, h, w, py, px);
    float fy = floorf(py), fx = floorf(px);
    int y0 = (int)fy, x0 = (int)fx;
    float ay = py - fy, ax = px - fx;
    float wlt = (1.f - ay) * (1.f - ax);
    float wrb = ay * ax;
    float wrt = (1.f - ay) * ax;
    float wlb = ay * (1.f - ax);

    const float* Xb = Xray + (size_t)b * CC * HDIM * WDIM;
    int i00 = y0 * WDIM + x0;
#pragma unroll
    for (int c = 0; c < CC; c++) {
        const float* p = Xb + (size_t)c * HDIM * WDIM;
        float v = wlt * p[i00] + wrt * p[i00 + 1]
                + wlb * p[i00 + WDIM] + wrb * p[i00 + WDIM + 1];
        xi[((size_t)(b * CC + c)) * NV + vox] = v;
    }
}

// ---------------------------------------------------------------------------
// 3x3x3 conv, pad 1, f32x2-packed over co-pairs, 4-voxel x-blocking,
// SOFTWARE-PIPELINED over cin with double-buffered SMEM (1 barrier per cin,
// global-load latency hidden behind compute). 128 thr; tile 16x8x4 out,
// halo 18x10x6 stored duplicated (v,v), row stride 19 (conflict-free LDS.64).
// MODE 0: +bias. MODE 1: +BN+leaky. MODE 2: fused offset(6)+mask(3), COUTP=10.
// ---------------------------------------------------------------------------
template<int CIN, int COUTP, int MODE>
__global__ __launch_bounds__(128)
void conv3_f2(const float* __restrict__ inA, const float* __restrict__ inB,
              const float* __restrict__ WtA, const float* __restrict__ bAv,
              const float* __restrict__ WtB, const float* __restrict__ bBv,
              float* __restrict__ out,
              const float* __restrict__ gamma, const float* __restrict__ beta,
              const float* __restrict__ mean, const float* __restrict__ var) {
    constexpr int NCP = COUTP / 2;
    constexpr int TILE_N = 1080;            // 6*10*18 halo voxels
    constexpr int NT = 9;                   // ceil(1080/128)
    constexpr int WN = 27 * COUTP;
    constexpr int NW = (WN + 127) / 128;
    __shared__ __align__(16) float2 s_t[2][6 * 10 * 19];
    __shared__ __align__(16) float  s_w[2][WN];

    int bi = blockIdx.x;
    int xt = bi & 3, yt = (bi >> 2) & 7, zt = (bi >> 5) & 15, b = bi >> 9;
    int tx = xt * 16, ty = yt * 8, tz = zt * 4;
    int tid = threadIdx.x;
    int lx4 = tid & 3, ly = (tid >> 2) & 7, lz = tid >> 5;

    float tr[NT];   // in-flight tile values for next cin
    float wr[NW];   // in-flight weights for next cin

    // load next-cin tile+weights into registers (global latency overlapped)
    auto load_regs = [&](int cin) {
        const float* src = (CIN == 32 && cin >= 16)
            ? inB + ((size_t)(b * 16 + (cin - 16))) * NV
            : inA + ((size_t)(b * 16 + cin)) * NV;
#pragma unroll
        for (int k = 0; k < NT; k++) {
            int i = tid + k * 128;
            float v = 0.f;
            if (i < TILE_N) {
                int z = i / 180, r = i - z * 180, y = r / 18, x = r - y * 18;
                int gz = tz + z - 1, gy = ty + y - 1, gx = tx + x - 1;
                if ((unsigned)gz < 64u && (unsigned)gy < 64u && (unsigned)gx < 64u)
                    v = src[(gz << 12) + (gy << 6) + gx];
            }
            tr[k] = v;
        }
#pragma unroll
        for (int k = 0; k < NW; k++) {
            int j = tid + k * 128;
            float wv = 0.f;
            if (j < WN) {
                int tap = j / COUTP, co = j - tap * COUTP;
                if (MODE == 2) {
                    wv = (co < 6) ? WtA[(size_t)co * (CIN * 27) + cin * 27 + tap]
                       : (co < 9) ? WtB[(size_t)(co - 6) * (CIN * 27) + cin * 27 + tap]
                       : 0.f;
                } else {
                    wv = WtA[(size_t)co * (CIN * 27) + cin * 27 + tap];
                }
            }
            wr[k] = wv;
        }
    };
    auto sts = [&](int p) {
#pragma unroll
        for (int k = 0; k < NT; k++) {
            int i = tid + k * 128;
            if (i < TILE_N) {
                int z = i / 180, r = i - z * 180, y = r / 18, x = r - y * 18;
                s_t[p][(z * 10 + y) * 19 + x] = make_float2(tr[k], tr[k]);
            }
        }
#pragma unroll
        for (int k = 0; k < NW; k++) {
            int j = tid + k * 128;
            if (j < WN) s_w[p][j] = wr[k];
        }
    };

    unsigned long long acc[NCP][4];
#pragma unroll
    for (int cp = 0; cp < NCP; cp++)
#pragma unroll
        for (int x = 0; x < 4; x++) acc[cp][x] = 0ull;

    load_regs(0);
    sts(0);
    __syncthreads();

    for (int cin = 0; cin < CIN; cin++) {
        int p = cin & 1;
        if (cin + 1 < CIN) load_regs(cin + 1);   // issue LDGs early

        const unsigned long long* wt =
            reinterpret_cast<const unsigned long long*>(s_w[p]);
        const float2* tp = s_t[p];
#pragma unroll
        for (int kd = 0; kd < 3; kd++)
#pragma unroll
            for (int kh = 0; kh < 3; kh++) {
                const unsigned long long* row =
                    reinterpret_cast<const unsigned long long*>(tp)
                    + ((lz + kd) * 10 + (ly + kh)) * 19 + lx4 * 4;
                unsigned long long vp[6];
#pragma unroll
                for (int j = 0; j < 6; j++) vp[j] = row[j];
#pragma unroll
                for (int kw = 0; kw < 3; kw++) {
                    int tb = (kd * 9 + kh * 3 + kw) * NCP;
#pragma unroll
                    for (int cp = 0; cp < NCP; cp++) {
                        unsigned long long w = wt[tb + cp];
                        acc[cp][0] = fma2(vp[kw + 0], w, acc[cp][0]);
                        acc[cp][1] = fma2(vp[kw + 1], w, acc[cp][1]);
                        acc[cp][2] = fma2(vp[kw + 2], w, acc[cp][2]);
                        acc[cp][3] = fma2(vp[kw + 3], w, acc[cp][3]);
                    }
                }
            }

        if (cin + 1 < CIN) sts(1 - p);           // STS after compute: LDG hidden
        __syncthreads();
    }

    int gx = tx + lx4 * 4, gy = ty + ly, gz = tz + lz;
    size_t vox = (size_t)((gz << 12) + (gy << 6) + gx);
    constexpr int OST = (MODE == 2) ? 9 : 16;
#pragma unroll
    for (int cp = 0; cp < NCP; cp++) {
        float2 a0 = *reinterpret_cast<float2*>(&acc[cp][0]);
        float2 a1 = *reinterpret_cast<float2*>(&acc[cp][1]);
        float2 a2 = *reinterpret_cast<float2*>(&acc[cp][2]);
        float2 a3 = *reinterpret_cast<float2*>(&acc[cp][3]);
#pragma unroll
        for (int half = 0; half < 2; half++) {
            int co = 2 * cp + half;
            if (MODE == 2 && co >= 9) continue;
            float4 o;
            o.x = half ? a0.y : a0.x;
            o.y = half ? a1.y : a1.x;
            o.z = half ? a2.y : a2.x;
            o.w = half ? a3.y : a3.x;
            float bia = (MODE == 2) ? ((co < 6) ? bAv[co] : bBv[co - 6]) : bAv[co];
            o.x += bia; o.y += bia; o.z += bia; o.w += bia;
            if (MODE == 1) {
                float sc = rsqrtf(var[co] + 1e-5f) * gamma[co];
                float mu = mean[co], be = beta[co];
                o.x = (o.x - mu) * sc + be; o.x = (o.x >= 0.f) ? o.x : 0.2f * o.x;
                o.y = (o.y - mu) * sc + be; o.y = (o.y >= 0.f) ? o.y : 0.2f * o.y;
                o.z = (o.z - mu) * sc + be; o.z = (o.z >= 0.f) ? o.z : 0.2f * o.z;
                o.w = (o.w - mu) * sc + be; o.w = (o.w >= 0.f) ? o.w : 0.2f * o.w;
            }
            *reinterpret_cast<float4*>(&out[((size_t)(b * OST + co)) * NV + vox]) = o;
        }
    }
}

// ---------------------------------------------------------------------------
// Kernel 3: softmax(mask) + deformable bilinear gather on the zero-padded
// 130x130 Xray; writes Xsum and the p_coor output (exact reference formulas).
// ---------------------------------------------------------------------------
__global__ void deform_kernel(const float* __restrict__ Xray, const float* __restrict__ om,
                              float* __restrict__ xsum, float* __restrict__ pcoor) {
    int idx = blockIdx.x * blockDim.x + threadIdx.x;
    if (idx >= BB * NV) return;
    int w = idx & 63, h = (idx >> 6) & 63, d = (idx >> 12) & 63, b = idx >> 18;
    int vox = idx & (NV - 1);

    const float* omb = om + (size_t)b * 9 * NV;
    float off[6];
#pragma unroll
    for (int j = 0; j < 6; j++) off[j] = omb[(size_t)j * NV + vox];
    float m0 = omb[(size_t)6 * NV + vox];
    float m1 = omb[(size_t)7 * NV + vox];
    float m2 = omb[(size_t)8 * NV + vox];
    float mx = fmaxf(m0, fmaxf(m1, m2));
    float e0 = expf(m0 - mx), e1 = expf(m1 - mx), e2 = expf(m2 - mx);
    float inv = 1.f / (e0 + e1 + e2);
    float mm[3] = { e0 * inv, e1 * inv, e2 * inv };

    float py0, px0;
    xray_coords(d, h, w, py0, px0);

    int   idx4[PPN][4];
    float wgt4[PPN][4];
#pragma unroll
    for (int p = 0; p < PPN; p++) {
        float py = fminf(fmaxf(off[p] + py0 + 1.f, 0.f), (float)(HDIM + 1));
        float px = fminf(fmaxf(off[PPN + p] + px0 + 1.f, 0.f), (float)(WDIM + 1));
        pcoor[(size_t)idx * 6 + p]        = py;
        pcoor[(size_t)idx * 6 + PPN + p]  = px;

        int fy = (int)floorf(py), fx = (int)floorf(px);
        int y0 = min(fy, HDIM + 1),     y1 = min(fy + 1, HDIM + 1);
        int x0 = min(fx, WDIM + 1),     x1 = min(fx + 1, WDIM + 1);
        float wy0 = 1.f + (float)y0 - py;
        float wy1 = 1.f - ((float)y1 - py);
        float wx0 = 1.f + (float)x0 - px;
        float wx1 = 1.f - ((float)x1 - px);

        int e00 = (y0 >= 1 && y0 <= HDIM && x0 >= 1 && x0 <= WDIM) ? ((y0 - 1) * WDIM + (x0 - 1)) : -1;
        int e11 = (y1 >= 1 && y1 <= HDIM && x1 >= 1 && x1 <= WDIM) ? ((y1 - 1) * WDIM + (x1 - 1)) : -1;
        int e01 = (y0 >= 1 && y0 <= HDIM && x1 >= 1 && x1 <= WDIM) ? ((y0 - 1) * WDIM + (x1 - 1)) : -1;
        int e10 = (y1 >= 1 && y1 <= HDIM && x0 >= 1 && x0 <= WDIM) ? ((y1 - 1) * WDIM + (x0 - 1)) : -1;
        idx4[p][0] = e00; idx4[p][1] = e11; idx4[p][2] = e01; idx4[p][3] = e10;
        wgt4[p][0] = mm[p] * wy0 * wx0;
        wgt4[p][1] = mm[p] * wy1 * wx1;
        wgt4[p][2] = mm[p] * wy0 * wx1;
        wgt4[p][3] = mm[p] * wy1 * wx0;
    }

    const float* Xb = Xray + (size_t)b * CC * HDIM * WDIM;
#pragma unroll
    for (int c = 0; c < CC; c++) {
        const float* pl = Xb + (size_t)c * HDIM * WDIM;
        float s = 0.f;
#pragma unroll
        for (int p = 0; p < PPN; p++)
#pragma unroll
            for (int q = 0; q < 4; q++) {
                int i4 = idx4[p][q];
                float v = (i4 >= 0) ? pl[i4] : 0.f;
                s += wgt4[p][q] * v;
            }
        xsum[((size_t)(b * CC + c)) * NV + vox] = s;
    }
}

// ---------------------------------------------------------------------------
// Launch. Output layout: [ conv2 out (B,C,D,H,W) | p_coor (B,D,H,W,6) ].
// ---------------------------------------------------------------------------
extern "C" void kernel_launch(void* const* d_in, const int* in_sizes, int n_in,
                              void* d_out, int out_size) {
    const float* CT    = (const float*)d_in[0];
    const float* Xray  = (const float*)d_in[1];
    const float* pW    = (const float*)d_in[2];
    const float* pb    = (const float*)d_in[3];
    const float* mW    = (const float*)d_in[4];
    const float* mb    = (const float*)d_in[5];
    const float* w1    = (const float*)d_in[6];
    const float* b1    = (const float*)d_in[7];
    const float* w2    = (const float*)d_in[8];
    const float* b2    = (const float*)d_in[9];
    const float* gamma = (const float*)d_in[10];
    const float* beta  = (const float*)d_in[11];
    const float* mean  = (const float*)d_in[12];
    const float* var   = (const float*)d_in[13];

    float* xi_p; cudaGetSymbolAddress((void**)&xi_p, g_xi);
    float* om_p; cudaGetSymbolAddress((void**)&om_p, g_om);
    float* xs_p; cudaGetSymbolAddress((void**)&xs_p, g_xsum);

    float* out   = (float*)d_out;
    float* pcoor = out + (size_t)BB * CC * NV;   // 8388608

    const int nthr = 256;
    const int nblk = (BB * NV + nthr - 1) / nthr;   // 2048
    const int cblk = 4 * 8 * 16 * BB;               // 1024 conv tiles

    // 1) xi = bilerp_single(Xrc, Xray)
    xi_kernel<<<nblk, nthr>>>(Xray, xi_p);
    // 2) fused offset(6)+mask(3) conv over [CT | xi]  (COUTP=10, ch 9 zero)
    conv3_f2<32, 10, 2><<<cblk, 128>>>(CT, xi_p, pW, pb, mW, mb, om_p,
                                       nullptr, nullptr, nullptr, nullptr);
    // 3) softmax + deformable gather -> Xsum, p_coor
    deform_kernel<<<nblk, nthr>>>(Xray, om_p, xs_p, pcoor);
    // 4) conv1 over [CT | Xsum] + BN + leaky -> h (reuses g_xi)
    conv3_f2<32, 16, 1><<<cblk, 128>>>(CT, xs_p, w1, b1, nullptr, nullptr, xi_p,
                                       gamma, beta, mean, var);
    // 5) conv2 (16->16) -> final output
    conv3_f2<16, 16, 0><<<cblk, 128>>>(xi_p, nullptr, w2, b2, nullptr, nullptr, out,
                                       nullptr, nullptr, nullptr, nullptr);
}